// round 1
// baseline (speedup 1.0000x reference)
#include <cuda_runtime.h>

#define VV 50000
#define TT 200
#define KEMB 512
#define BB 2048
#define TK 20

// scratch (static device allocations are the sanctioned workaround)
__device__ float g_wt[TT * VV];      // wt, then beta in-place (40 MB)
__device__ float g_topv[TT * TK];    // normalized top-k values
__device__ int   g_topi[TT * TK];    // top-k indices
__device__ float g_sq[TT];           // per-row sum of squares of normalized top-k

// ---------------- theta = softmax(alpha, axis=-1) ----------------
__global__ void theta_kernel(const float* __restrict__ alpha, float* __restrict__ theta) {
    int row = blockIdx.x;
    int tid = threadIdx.x;
    __shared__ float red[256];
    float x = (tid < TT) ? alpha[row * TT + tid] : -1e30f;
    red[tid] = x;
    __syncthreads();
    for (int s = 128; s > 0; s >>= 1) {
        if (tid < s) red[tid] = fmaxf(red[tid], red[tid + s]);
        __syncthreads();
    }
    float m = red[0];
    __syncthreads();
    float e = (tid < TT) ? __expf(x - m) : 0.f;
    red[tid] = e;
    __syncthreads();
    for (int s = 128; s > 0; s >>= 1) {
        if (tid < s) red[tid] += red[tid + s];
        __syncthreads();
    }
    float inv = 1.f / red[0];
    if (tid < TT) theta[row * TT + tid] = e * inv;
}

// ---------------- wt = topic_emb[200,512] @ word_emb[512,50000] ----------------
__global__ __launch_bounds__(256) void wt_gemm_kernel(const float* __restrict__ A,
                                                      const float* __restrict__ Bm) {
    __shared__ float As[16 * 132];
    __shared__ float Bs[16 * 128];
    const int tx = threadIdx.x, ty = threadIdx.y;
    const int tid = ty * 16 + tx;
    const int bn = blockIdx.x * 128;
    const int bm = blockIdx.y * 128;
    float acc[8][8] = {};
    for (int k0 = 0; k0 < KEMB; k0 += 16) {
        for (int i = tid; i < 128 * 16; i += 256) {
            int m = i >> 4, k = i & 15;
            int gr = bm + m;
            As[k * 132 + m] = (gr < TT) ? A[gr * KEMB + k0 + k] : 0.f;
        }
        for (int i = tid; i < 16 * 128; i += 256) {
            int k = i >> 7, n = i & 127;
            int gc = bn + n;
            Bs[k * 128 + n] = (gc < VV) ? Bm[(size_t)(k0 + k) * VV + gc] : 0.f;
        }
        __syncthreads();
        #pragma unroll
        for (int k = 0; k < 16; k++) {
            float4 a0 = *reinterpret_cast<const float4*>(&As[k * 132 + ty * 8]);
            float4 a1 = *reinterpret_cast<const float4*>(&As[k * 132 + ty * 8 + 4]);
            float4 b0 = *reinterpret_cast<const float4*>(&Bs[k * 128 + tx * 8]);
            float4 b1 = *reinterpret_cast<const float4*>(&Bs[k * 128 + tx * 8 + 4]);
            float af[8] = {a0.x,a0.y,a0.z,a0.w,a1.x,a1.y,a1.z,a1.w};
            float bf[8] = {b0.x,b0.y,b0.z,b0.w,b1.x,b1.y,b1.z,b1.w};
            #pragma unroll
            for (int i = 0; i < 8; i++)
                #pragma unroll
                for (int j = 0; j < 8; j++)
                    acc[i][j] += af[i] * bf[j];
        }
        __syncthreads();
    }
    #pragma unroll
    for (int i = 0; i < 8; i++) {
        int row = bm + ty * 8 + i;
        if (row < TT) {
            #pragma unroll
            for (int j = 0; j < 8; j++) {
                int col = bn + tx * 8 + j;
                if (col < VV) g_wt[(size_t)row * VV + col] = acc[i][j];
            }
        }
    }
}

// ---------------- beta = softmax over vocab, in-place on g_wt ----------------
__global__ void beta_softmax_kernel() {
    int row = blockIdx.x;
    float* p = g_wt + (size_t)row * VV;
    int tid = threadIdx.x;
    __shared__ float red[512];
    float m = -1e30f;
    for (int j = tid; j < VV; j += 512) m = fmaxf(m, p[j]);
    red[tid] = m;
    __syncthreads();
    for (int s = 256; s > 0; s >>= 1) {
        if (tid < s) red[tid] = fmaxf(red[tid], red[tid + s]);
        __syncthreads();
    }
    m = red[0];
    __syncthreads();
    float s = 0.f;
    for (int j = tid; j < VV; j += 512) {
        float e = __expf(p[j] - m);
        p[j] = e;
        s += e;
    }
    red[tid] = s;
    __syncthreads();
    for (int st = 256; st > 0; st >>= 1) {
        if (tid < st) red[tid] += red[tid + st];
        __syncthreads();
    }
    float inv = 1.f / red[0];
    for (int j = tid; j < VV; j += 512) p[j] *= inv;
}

// ---------------- per-topic top-20 (jax top_k tie-break: lower index first) ----------------
__global__ void topk_kernel() {
    int row = blockIdx.x;
    int tid = threadIdx.x;
    const float* p = g_wt + (size_t)row * VV;
    float lv[TK]; int li[TK];
    #pragma unroll
    for (int t = 0; t < TK; t++) { lv[t] = -1e30f; li[t] = 0x7fffffff; }
    for (int j = tid; j < VV; j += 256) {
        float x = p[j];
        bool better = (x > lv[TK-1]) || (x == lv[TK-1] && j < li[TK-1]);
        if (better) {
            int pos = TK - 1;
            while (pos > 0 && (x > lv[pos-1] || (x == lv[pos-1] && j < li[pos-1]))) {
                lv[pos] = lv[pos-1]; li[pos] = li[pos-1]; pos--;
            }
            lv[pos] = x; li[pos] = j;
        }
    }
    __shared__ float hv[256]; __shared__ int hj[256]; __shared__ int ht[256];
    __shared__ float selv[TK]; __shared__ int seli[TK];
    int ptr = 0;
    for (int r = 0; r < TK; r++) {
        hv[tid] = (ptr < TK) ? lv[ptr] : -1e30f;
        hj[tid] = (ptr < TK) ? li[ptr] : 0x7fffffff;
        ht[tid] = tid;
        __syncthreads();
        for (int s = 128; s > 0; s >>= 1) {
            if (tid < s) {
                bool take = (hv[tid+s] > hv[tid]) ||
                            (hv[tid+s] == hv[tid] && hj[tid+s] < hj[tid]);
                if (take) { hv[tid] = hv[tid+s]; hj[tid] = hj[tid+s]; ht[tid] = ht[tid+s]; }
            }
            __syncthreads();
        }
        if (tid == ht[0]) ptr++;
        if (tid == 0) { selv[r] = hv[0]; seli[r] = hj[0]; }
        __syncthreads();
    }
    if (tid == 0) {
        float s = 0.f;
        for (int r = 0; r < TK; r++) s += selv[r];
        float inv = 1.f / s, sq = 0.f;
        for (int r = 0; r < TK; r++) {
            float nv = selv[r] * inv;
            g_topv[row * TK + r] = nv;
            g_topi[row * TK + r] = seli[r];
            sq += nv * nv;
        }
        g_sq[row] = sq;
    }
}

// ---------------- STDR via sparse gram on top-k rows ----------------
__global__ void stdr_kernel(float* __restrict__ out_stdr) {
    int i = blockIdx.x;
    int tid = threadIdx.x;
    __shared__ float vi[TK]; __shared__ int ii[TK];
    __shared__ float red[256];
    if (tid < TK) { vi[tid] = g_topv[i * TK + tid]; ii[tid] = g_topi[i * TK + tid]; }
    __syncthreads();
    float part = 0.f;
    float sqi = g_sq[i];
    for (int j = tid; j < TT; j += 256) {
        float g = 0.f;
        for (int b = 0; b < TK; b++) {
            int jb = g_topi[j * TK + b];
            float vb = g_topv[j * TK + b];
            #pragma unroll
            for (int a = 0; a < TK; a++)
                if (ii[a] == jb) g += vi[a] * vb;
        }
        float d2 = sqi + g_sq[j] - 2.f * g;
        part += 0.5f * fmaxf(d2, 0.f);
    }
    red[tid] = part;
    __syncthreads();
    for (int s = 128; s > 0; s >>= 1) {
        if (tid < s) red[tid] += red[tid + s];
        __syncthreads();
    }
    if (tid == 0) atomicAdd(out_stdr, red[0] * (1.f / ((float)TT * (float)TT)));
}

// ---------------- fused: Re[b] = -sum_v log(theta@beta) * doc_bow ----------------
__global__ __launch_bounds__(256) void fused_re_kernel(const float* __restrict__ theta,
                                                       const float* __restrict__ dbow,
                                                       float* __restrict__ Re) {
    extern __shared__ float smem[];
    float* theta_s = smem;             // [200][132] padded, k-major
    float* beta_s  = smem + TT * 132;  // [200][128]
    const int tx = threadIdx.x, ty = threadIdx.y;
    const int tid = ty * 16 + tx;
    const int bm = blockIdx.y * 128;
    for (int i = tid; i < 128 * TT; i += 256) {
        int m = i / TT, k = i % TT;
        theta_s[k * 132 + m] = theta[(size_t)(bm + m) * TT + k];
    }
    float re[8] = {};
    const int CH = 4;
    for (int c = 0; c < CH; c++) {
        int chunk = blockIdx.x * CH + c;
        int vb = chunk * 128;
        if (vb >= VV) break;
        __syncthreads();
        for (int i = tid; i < TT * 128; i += 256) {
            int k = i >> 7, n = i & 127;
            int v = vb + n;
            beta_s[k * 128 + n] = (v < VV) ? g_wt[(size_t)k * VV + v] : 0.f;
        }
        __syncthreads();
        float acc[8][8] = {};
        #pragma unroll 2
        for (int k = 0; k < TT; k++) {
            float4 a0 = *reinterpret_cast<const float4*>(&theta_s[k * 132 + ty * 8]);
            float4 a1 = *reinterpret_cast<const float4*>(&theta_s[k * 132 + ty * 8 + 4]);
            float4 b0 = *reinterpret_cast<const float4*>(&beta_s[k * 128 + tx * 8]);
            float4 b1 = *reinterpret_cast<const float4*>(&beta_s[k * 128 + tx * 8 + 4]);
            float af[8] = {a0.x,a0.y,a0.z,a0.w,a1.x,a1.y,a1.z,a1.w};
            float bf[8] = {b0.x,b0.y,b0.z,b0.w,b1.x,b1.y,b1.z,b1.w};
            #pragma unroll
            for (int i = 0; i < 8; i++)
                #pragma unroll
                for (int j = 0; j < 8; j++)
                    acc[i][j] += af[i] * bf[j];
        }
        int v0 = vb + tx * 8;
        #pragma unroll
        for (int i = 0; i < 8; i++) {
            int row = bm + ty * 8 + i;
            const float* db = dbow + (size_t)row * VV + v0;
            if (v0 + 7 < VV) {
                float4 d0 = *reinterpret_cast<const float4*>(db);
                float4 d1 = *reinterpret_cast<const float4*>(db + 4);
                re[i] -= __logf(acc[i][0]) * d0.x + __logf(acc[i][1]) * d0.y
                       + __logf(acc[i][2]) * d0.z + __logf(acc[i][3]) * d0.w
                       + __logf(acc[i][4]) * d1.x + __logf(acc[i][5]) * d1.y
                       + __logf(acc[i][6]) * d1.z + __logf(acc[i][7]) * d1.w;
            } else {
                #pragma unroll
                for (int j = 0; j < 8; j++)
                    if (v0 + j < VV) re[i] -= __logf(acc[i][j]) * db[j];
            }
        }
    }
    __syncthreads();
    float* rs = smem;  // reuse: [128][17]
    #pragma unroll
    for (int i = 0; i < 8; i++) rs[(ty * 8 + i) * 17 + tx] = re[i];
    __syncthreads();
    if (tid < 128) {
        float s = 0.f;
        #pragma unroll
        for (int t = 0; t < 16; t++) s += rs[tid * 17 + t];
        atomicAdd(&Re[bm + tid], s);
    }
}

extern "C" void kernel_launch(void* const* d_in, const int* in_sizes, int n_in,
                              void* d_out, int out_size) {
    (void)in_sizes; (void)n_in; (void)out_size;
    const float* alpha = (const float*)d_in[0];
    const float* dbow  = (const float*)d_in[1];
    const float* temb  = (const float*)d_in[2];
    const float* wemb  = (const float*)d_in[3];
    float* out   = (float*)d_out;
    float* Re    = out;            // [0 .. 2047]
    float* stdr  = out + BB;       // [2048]
    float* theta = out + BB + 1;   // [2049 .. 2049+409599]

    cudaMemsetAsync(out, 0, (BB + 1) * sizeof(float));

    theta_kernel<<<BB, 256>>>(alpha, theta);

    {
        dim3 blk(16, 16);
        dim3 grd((VV + 127) / 128, (TT + 127) / 128);
        wt_gemm_kernel<<<grd, blk>>>(temb, wemb);
    }

    beta_softmax_kernel<<<TT, 512>>>();
    topk_kernel<<<TT, 256>>>();
    stdr_kernel<<<TT, 256>>>(stdr);

    {
        dim3 blk(16, 16);
        dim3 grd(98, BB / 128);  // 391 v-chunks of 128, 4 per block
        size_t sm = (size_t)(TT * 132 + TT * 128) * sizeof(float);
        cudaFuncSetAttribute(fused_re_kernel,
                             cudaFuncAttributeMaxDynamicSharedMemorySize, (int)sm);
        fused_re_kernel<<<grd, blk, sm>>>(theta, dbow, Re);
    }
}

// round 2
// speedup vs baseline: 3.7007x; 3.7007x over previous
#include <cuda_runtime.h>
#include <cuda_bf16.h>
#include <cstdint>

#define VV 50000
#define VVP 50048            // padded vocab (for bf16 buffers)
#define TT 200
#define TTP 208              // padded topic dim (13 * 16)
#define KEMB 512
#define BB 2048
#define TK 20
#define NSEG 8
#define SEGLEN 6250          // 50000 / 8

// ------------------------- static device scratch -------------------------
__device__ float g_wt[(size_t)TT * VV];                 // wt, then e=exp(wt-max) in place (40MB)
__device__ __nv_bfloat16 g_wtb[(size_t)TTP * VVP];      // beta bf16, padded (20.8MB)
__device__ __nv_bfloat16 g_wb[(size_t)KEMB * VVP];      // word_emb bf16 padded (51.2MB)
__device__ __nv_bfloat16 g_ta[256 * KEMB];              // topic_emb bf16 padded to 256 rows
__device__ __nv_bfloat16 g_thb[(size_t)BB * TTP];       // theta bf16 padded
__device__ float g_segmax[TT * NSEG];
__device__ float g_segsum[TT * NSEG];
__device__ float g_cand_v[TT * NSEG * TK];
__device__ int   g_cand_i[TT * NSEG * TK];
__device__ float g_topv[TT * TK];
__device__ int   g_topi[TT * TK];
__device__ float g_sq[TT];
__device__ float g_rowinv[TT];

// ------------------------- PTX helpers -------------------------
__device__ __forceinline__ uint32_t smem_u32(const void* p) {
    return (uint32_t)__cvta_generic_to_shared(p);
}
__device__ __forceinline__ void ldsm_x4(uint32_t& r0, uint32_t& r1, uint32_t& r2, uint32_t& r3,
                                        uint32_t addr) {
    asm volatile("ldmatrix.sync.aligned.m8n8.x4.shared.b16 {%0,%1,%2,%3}, [%4];\n"
                 : "=r"(r0), "=r"(r1), "=r"(r2), "=r"(r3) : "r"(addr));
}
__device__ __forceinline__ void mma_bf16(float* d, const uint32_t* a, const uint32_t* b) {
    asm volatile(
        "mma.sync.aligned.m16n8k16.row.col.f32.bf16.bf16.f32 "
        "{%0,%1,%2,%3},{%4,%5,%6,%7},{%8,%9},{%0,%1,%2,%3};\n"
        : "+f"(d[0]), "+f"(d[1]), "+f"(d[2]), "+f"(d[3])
        : "r"(a[0]), "r"(a[1]), "r"(a[2]), "r"(a[3]), "r"(b[0]), "r"(b[1]));
}
__device__ __forceinline__ unsigned long long makekey(float v, int i) {
    return ((unsigned long long)__float_as_uint(v) << 32) |
           (unsigned long long)(0xFFFFFFFFu - (unsigned)i);
}

// ------------------------- theta = softmax(alpha) (+ bf16 copy) -------------------------
__global__ void theta_kernel(const float* __restrict__ alpha, float* __restrict__ theta) {
    int row = blockIdx.x;
    int tid = threadIdx.x;
    __shared__ float red[256];
    float x = (tid < TT) ? alpha[row * TT + tid] : -1e30f;
    red[tid] = x;
    __syncthreads();
    for (int s = 128; s > 0; s >>= 1) {
        if (tid < s) red[tid] = fmaxf(red[tid], red[tid + s]);
        __syncthreads();
    }
    float m = red[0];
    __syncthreads();
    float e = (tid < TT) ? __expf(x - m) : 0.f;
    red[tid] = e;
    __syncthreads();
    for (int s = 128; s > 0; s >>= 1) {
        if (tid < s) red[tid] += red[tid + s];
        __syncthreads();
    }
    float inv = 1.f / red[0];
    if (tid < TT) {
        float t = e * inv;
        theta[row * TT + tid] = t;
        g_thb[(size_t)row * TTP + tid] = __float2bfloat16(t);
    } else if (tid < TTP) {
        g_thb[(size_t)row * TTP + tid] = __float2bfloat16(0.f);
    }
}

// ------------------------- bf16 conversions -------------------------
__global__ void conv_ta(const float* __restrict__ temb) {
    int i = blockIdx.x * 256 + threadIdx.x;
    if (i < 256 * KEMB) {
        int r = i >> 9, c = i & 511;
        float v = (r < TT) ? temb[r * KEMB + c] : 0.f;
        g_ta[i] = __float2bfloat16(v);
    }
}
__global__ void conv_wb(const float* __restrict__ wemb) {
    int idx = blockIdx.x * 256 + threadIdx.x;
    const int PP = VVP / 2;
    if (idx >= KEMB * PP) return;
    int r = idx / PP, pc = idx % PP;
    int c = pc * 2;
    float2 v = make_float2(0.f, 0.f);
    if (c < VV) v = *reinterpret_cast<const float2*>(wemb + (size_t)r * VV + c);
    *reinterpret_cast<__nv_bfloat162*>(g_wb + (size_t)r * VVP + c) =
        __floats2bfloat162_rn(v.x, v.y);
}

// ------------------------- wt = topic_emb @ word_emb via mma (bf16) -------------------------
__global__ __launch_bounds__(256) void wt_mma_kernel() {
    __shared__ __align__(16) __nv_bfloat16 As[2][128 * 24];
    __shared__ __align__(16) __nv_bfloat16 Bs[2][16 * 136];
    const int tid = threadIdx.x, lane = tid & 31, wid = tid >> 5;
    const int warp_m = wid >> 2, warp_n = wid & 3;
    const int bm = blockIdx.y * 128, vb = blockIdx.x * 128;
    const int a_row = tid >> 1, a_half = tid & 1;
    const int b_row = tid >> 4, b_seg = tid & 15;

    uint4 ra = *reinterpret_cast<const uint4*>(g_ta + (size_t)(bm + a_row) * KEMB + a_half * 8);
    uint4 rb = *reinterpret_cast<const uint4*>(g_wb + (size_t)b_row * VVP + vb + b_seg * 8);
    *reinterpret_cast<uint4*>(&As[0][a_row * 24 + a_half * 8]) = ra;
    *reinterpret_cast<uint4*>(&Bs[0][b_row * 136 + b_seg * 8]) = rb;
    __syncthreads();

    float acc[4][4][4] = {};
    const int a_off = ((warp_m * 64 + (lane & 15)) * 24 + (lane >> 4) * 8) * 2;
    const int b_off = (((lane & 7) + ((lane >> 3) & 1) * 8) * 136 + warp_n * 32 + (lane >> 4) * 8) * 2;

    const int NK = KEMB / 16;
    for (int c = 0; c < NK; ++c) {
        if (c < NK - 1) {
            int k0 = (c + 1) * 16;
            ra = *reinterpret_cast<const uint4*>(g_ta + (size_t)(bm + a_row) * KEMB + k0 + a_half * 8);
            rb = *reinterpret_cast<const uint4*>(g_wb + (size_t)(k0 + b_row) * VVP + vb + b_seg * 8);
        }
        int cur = c & 1;
        uint32_t ab = smem_u32(&As[cur][0]) + a_off;
        uint32_t bb = smem_u32(&Bs[cur][0]) + b_off;
        uint32_t a[4][4], b[4][2];
        #pragma unroll
        for (int mi = 0; mi < 4; mi++)
            ldsm_x4(a[mi][0], a[mi][1], a[mi][2], a[mi][3], ab + mi * 16 * 24 * 2);
        ldsm_x4(b[0][0], b[0][1], b[1][0], b[1][1], bb);
        ldsm_x4(b[2][0], b[2][1], b[3][0], b[3][1], bb + 32);
        #pragma unroll
        for (int mi = 0; mi < 4; mi++)
            #pragma unroll
            for (int ni = 0; ni < 4; ni++)
                mma_bf16(acc[mi][ni], a[mi], b[ni]);
        if (c < NK - 1) {
            int nxt = 1 - cur;
            *reinterpret_cast<uint4*>(&As[nxt][a_row * 24 + a_half * 8]) = ra;
            *reinterpret_cast<uint4*>(&Bs[nxt][b_row * 136 + b_seg * 8]) = rb;
            __syncthreads();
        }
    }
    #pragma unroll
    for (int mi = 0; mi < 4; mi++) {
        int r0 = bm + warp_m * 64 + mi * 16 + (lane >> 2);
        #pragma unroll
        for (int ni = 0; ni < 4; ni++) {
            int n0 = vb + warp_n * 32 + ni * 8 + (lane & 3) * 2;
            if (n0 < VV) {
                if (r0 < TT) {
                    float2 s = make_float2(acc[mi][ni][0], acc[mi][ni][1]);
                    *reinterpret_cast<float2*>(g_wt + (size_t)r0 * VV + n0) = s;
                }
                if (r0 + 8 < TT) {
                    float2 s = make_float2(acc[mi][ni][2], acc[mi][ni][3]);
                    *reinterpret_cast<float2*>(g_wt + (size_t)(r0 + 8) * VV + n0) = s;
                }
            }
        }
    }
}

// ------------------------- per-(row,segment) max -------------------------
__global__ void rowmax_seg() {
    int row = blockIdx.y, seg = blockIdx.x;
    int tid = threadIdx.x, lane = tid & 31, wid = tid >> 5;
    const float* p = g_wt + (size_t)row * VV + seg * SEGLEN;
    float m = -1e30f;
    for (int i = tid; i < SEGLEN; i += 256) m = fmaxf(m, p[i]);
    #pragma unroll
    for (int off = 16; off > 0; off >>= 1) m = fmaxf(m, __shfl_xor_sync(0xffffffff, m, off));
    __shared__ float wm[8];
    if (lane == 0) wm[wid] = m;
    __syncthreads();
    if (tid == 0) {
        float t = wm[0];
        #pragma unroll
        for (int i = 1; i < 8; i++) t = fmaxf(t, wm[i]);
        g_segmax[row * NSEG + seg] = t;
    }
}

// ------------------------- exp + sum + segment top-20 -------------------------
__global__ __launch_bounds__(256) void expsum_topk_seg() {
    int row = blockIdx.y, seg = blockIdx.x;
    int tid = threadIdx.x, lane = tid & 31, wid = tid >> 5;
    float m = g_segmax[row * NSEG];
    #pragma unroll
    for (int s = 1; s < NSEG; s++) m = fmaxf(m, g_segmax[row * NSEG + s]);
    float* p = g_wt + (size_t)row * VV + seg * SEGLEN;
    const int base = seg * SEGLEN;

    float lv[TK]; int li[TK];
    #pragma unroll
    for (int t = 0; t < TK; t++) { lv[t] = -1.f; li[t] = 0x7fffffff; }
    float ssum = 0.f;
    for (int i = tid; i < SEGLEN; i += 256) {
        float e = __expf(p[i] - m);
        p[i] = e;
        ssum += e;
        if (e > lv[TK - 1]) {
            int pos = TK - 1;
            while (pos > 0 && e > lv[pos - 1]) {
                lv[pos] = lv[pos - 1]; li[pos] = li[pos - 1]; pos--;
            }
            lv[pos] = e; li[pos] = base + i;
        }
    }
    // sum reduce
    #pragma unroll
    for (int off = 16; off > 0; off >>= 1) ssum += __shfl_xor_sync(0xffffffff, ssum, off);
    __shared__ float wsum[8];
    if (lane == 0) wsum[wid] = ssum;

    // warp-level top-20 merge (per-thread lists are sorted desc)
    __shared__ float wv8[8][TK];
    __shared__ int   wi8[8][TK];
    int ptr = 0;
    for (int r = 0; r < TK; r++) {
        unsigned long long key = (ptr < TK) ? makekey(lv[ptr], li[ptr]) : 0ULL;
        unsigned long long k = key;
        #pragma unroll
        for (int off = 16; off > 0; off >>= 1) {
            unsigned long long o = __shfl_xor_sync(0xffffffff, k, off);
            if (o > k) k = o;
        }
        if (key == k && key != 0ULL) ptr++;
        if (lane == 0) {
            wv8[wid][r] = __uint_as_float((unsigned)(k >> 32));
            wi8[wid][r] = (int)(0xFFFFFFFFu - (unsigned)(k & 0xFFFFFFFFu));
        }
    }
    __syncthreads();
    if (tid == 0) {
        float t = 0.f;
        #pragma unroll
        for (int i = 0; i < 8; i++) t += wsum[i];
        g_segsum[row * NSEG + seg] = t;
    }
    if (wid == 0) {
        unsigned long long ck[5];
        #pragma unroll
        for (int j = 0; j < 5; j++) {
            int q = lane * 5 + j;
            ck[j] = makekey(wv8[q / TK][q % TK], wi8[q / TK][q % TK]);
        }
        for (int r = 0; r < TK; r++) {
            unsigned long long best = 0ULL; int bj = -1;
            #pragma unroll
            for (int j = 0; j < 5; j++)
                if (ck[j] > best) { best = ck[j]; bj = j; }
            unsigned long long k = best;
            #pragma unroll
            for (int off = 16; off > 0; off >>= 1) {
                unsigned long long o = __shfl_xor_sync(0xffffffff, k, off);
                if (o > k) k = o;
            }
            if (bj >= 0 && ck[bj] == k) ck[bj] = 0ULL;
            if (lane == 0) {
                g_cand_v[(row * NSEG + seg) * TK + r] = __uint_as_float((unsigned)(k >> 32));
                g_cand_i[(row * NSEG + seg) * TK + r] = (int)(0xFFFFFFFFu - (unsigned)(k & 0xFFFFFFFFu));
            }
        }
    }
}

// ------------------------- merge 8x20 candidates -> top-20, normalize -------------------------
__global__ void candmerge_kernel() {
    int row = blockIdx.x;
    int lane = threadIdx.x;
    unsigned long long ck[5];
    #pragma unroll
    for (int j = 0; j < 5; j++) {
        int q = lane * 5 + j;
        ck[j] = makekey(g_cand_v[row * (NSEG * TK) + q], g_cand_i[row * (NSEG * TK) + q]);
    }
    float selv[TK]; int seli[TK];
    for (int r = 0; r < TK; r++) {
        unsigned long long best = 0ULL; int bj = -1;
        #pragma unroll
        for (int j = 0; j < 5; j++)
            if (ck[j] > best) { best = ck[j]; bj = j; }
        unsigned long long k = best;
        #pragma unroll
        for (int off = 16; off > 0; off >>= 1) {
            unsigned long long o = __shfl_xor_sync(0xffffffff, k, off);
            if (o > k) k = o;
        }
        if (bj >= 0 && ck[bj] == k) ck[bj] = 0ULL;
        selv[r] = __uint_as_float((unsigned)(k >> 32));
        seli[r] = (int)(0xFFFFFFFFu - (unsigned)(k & 0xFFFFFFFFu));
    }
    if (lane == 0) {
        float s = 0.f;
        #pragma unroll
        for (int r = 0; r < TK; r++) s += selv[r];
        float inv = 1.f / s, sq = 0.f;
        #pragma unroll
        for (int r = 0; r < TK; r++) {
            float nv = selv[r] * inv;
            g_topv[row * TK + r] = nv;
            g_topi[row * TK + r] = seli[r];
            sq += nv * nv;
        }
        g_sq[row] = sq;
        float bs = 0.f;
        #pragma unroll
        for (int s8 = 0; s8 < NSEG; s8++) bs += g_segsum[row * NSEG + s8];
        g_rowinv[row] = 1.f / bs;
    }
}

// ------------------------- STDR via sparse gram -------------------------
__global__ void stdr_kernel(float* __restrict__ out_stdr) {
    int i = blockIdx.x;
    int tid = threadIdx.x;
    __shared__ float vi[TK]; __shared__ int ii[TK];
    __shared__ float red[256];
    if (tid < TK) { vi[tid] = g_topv[i * TK + tid]; ii[tid] = g_topi[i * TK + tid]; }
    __syncthreads();
    float part = 0.f;
    float sqi = g_sq[i];
    for (int j = tid; j < TT; j += 256) {
        float g = 0.f;
        for (int b = 0; b < TK; b++) {
            int jb = g_topi[j * TK + b];
            float vb = g_topv[j * TK + b];
            #pragma unroll
            for (int a = 0; a < TK; a++)
                if (ii[a] == jb) g += vi[a] * vb;
        }
        float d2 = sqi + g_sq[j] - 2.f * g;
        part += 0.5f * fmaxf(d2, 0.f);
    }
    red[tid] = part;
    __syncthreads();
    for (int s = 128; s > 0; s >>= 1) {
        if (tid < s) red[tid] += red[tid + s];
        __syncthreads();
    }
    if (tid == 0) atomicAdd(out_stdr, red[0] * (1.f / ((float)TT * (float)TT)));
}

// ------------------------- beta -> bf16 (normalized, padded) -------------------------
__global__ void normalize_bf16() {
    int idx = blockIdx.x * 256 + threadIdx.x;
    const int PP = VVP / 2;
    if (idx >= TTP * PP) return;
    int row = idx / PP, pc = idx % PP;
    int c = pc * 2;
    __nv_bfloat162 out;
    if (row < TT && c < VV) {
        float inv = g_rowinv[row];
        float2 e = *reinterpret_cast<const float2*>(g_wt + (size_t)row * VV + c);
        out = __floats2bfloat162_rn(e.x * inv, e.y * inv);
    } else {
        out = __floats2bfloat162_rn(0.f, 0.f);
    }
    *reinterpret_cast<__nv_bfloat162*>(g_wtb + (size_t)row * VVP + c) = out;
}

// ------------------------- fused Re: mma (theta_b @ beta_b) + log + dot(dbow) -------------------------
__global__ __launch_bounds__(256) void fused_re_mma(const float* __restrict__ dbow,
                                                    float* __restrict__ Re) {
    __shared__ __align__(16) __nv_bfloat16 As[2][128 * 24];
    __shared__ __align__(16) __nv_bfloat16 Bs[2][16 * 136];
    __shared__ float sre[128];
    const int tid = threadIdx.x, lane = tid & 31, wid = tid >> 5;
    const int warp_m = wid >> 2, warp_n = wid & 3;
    const int bm = blockIdx.y * 128, vb = blockIdx.x * 128;
    const int a_row = tid >> 1, a_half = tid & 1;
    const int b_row = tid >> 4, b_seg = tid & 15;

    uint4 ra = *reinterpret_cast<const uint4*>(g_thb + (size_t)(bm + a_row) * TTP + a_half * 8);
    uint4 rb = *reinterpret_cast<const uint4*>(g_wtb + (size_t)b_row * VVP + vb + b_seg * 8);
    *reinterpret_cast<uint4*>(&As[0][a_row * 24 + a_half * 8]) = ra;
    *reinterpret_cast<uint4*>(&Bs[0][b_row * 136 + b_seg * 8]) = rb;
    if (tid < 128) sre[tid] = 0.f;
    __syncthreads();

    float acc[4][4][4] = {};
    const int a_off = ((warp_m * 64 + (lane & 15)) * 24 + (lane >> 4) * 8) * 2;
    const int b_off = (((lane & 7) + ((lane >> 3) & 1) * 8) * 136 + warp_n * 32 + (lane >> 4) * 8) * 2;

    const int NK = TTP / 16;  // 13
    for (int c = 0; c < NK; ++c) {
        if (c < NK - 1) {
            int k0 = (c + 1) * 16;
            ra = *reinterpret_cast<const uint4*>(g_thb + (size_t)(bm + a_row) * TTP + k0 + a_half * 8);
            rb = *reinterpret_cast<const uint4*>(g_wtb + (size_t)(k0 + b_row) * VVP + vb + b_seg * 8);
        }
        int cur = c & 1;
        uint32_t ab = smem_u32(&As[cur][0]) + a_off;
        uint32_t bb = smem_u32(&Bs[cur][0]) + b_off;
        uint32_t a[4][4], b[4][2];
        #pragma unroll
        for (int mi = 0; mi < 4; mi++)
            ldsm_x4(a[mi][0], a[mi][1], a[mi][2], a[mi][3], ab + mi * 16 * 24 * 2);
        ldsm_x4(b[0][0], b[0][1], b[1][0], b[1][1], bb);
        ldsm_x4(b[2][0], b[2][1], b[3][0], b[3][1], bb + 32);
        #pragma unroll
        for (int mi = 0; mi < 4; mi++)
            #pragma unroll
            for (int ni = 0; ni < 4; ni++)
                mma_bf16(acc[mi][ni], a[mi], b[ni]);
        if (c < NK - 1) {
            int nxt = 1 - cur;
            *reinterpret_cast<uint4*>(&As[nxt][a_row * 24 + a_half * 8]) = ra;
            *reinterpret_cast<uint4*>(&Bs[nxt][b_row * 136 + b_seg * 8]) = rb;
            __syncthreads();
        }
    }

    // epilogue: -log(logit) * dbow, reduce to per-row sums
    #pragma unroll
    for (int mi = 0; mi < 4; mi++) {
        int r0 = bm + warp_m * 64 + mi * 16 + (lane >> 2);
        float p0 = 0.f, p1 = 0.f;
        #pragma unroll
        for (int ni = 0; ni < 4; ni++) {
            int n0 = vb + warp_n * 32 + ni * 8 + (lane & 3) * 2;
            if (n0 < VV) {
                float2 d0 = *reinterpret_cast<const float2*>(dbow + (size_t)r0 * VV + n0);
                p0 -= __logf(acc[mi][ni][0]) * d0.x + __logf(acc[mi][ni][1]) * d0.y;
                float2 d1 = *reinterpret_cast<const float2*>(dbow + (size_t)(r0 + 8) * VV + n0);
                p1 -= __logf(acc[mi][ni][2]) * d1.x + __logf(acc[mi][ni][3]) * d1.y;
            }
        }
        p0 += __shfl_xor_sync(0xffffffff, p0, 1);
        p0 += __shfl_xor_sync(0xffffffff, p0, 2);
        p1 += __shfl_xor_sync(0xffffffff, p1, 1);
        p1 += __shfl_xor_sync(0xffffffff, p1, 2);
        if ((lane & 3) == 0) {
            int rl = warp_m * 64 + mi * 16 + (lane >> 2);
            atomicAdd(&sre[rl], p0);
            atomicAdd(&sre[rl + 8], p1);
        }
    }
    __syncthreads();
    if (tid < 128) atomicAdd(&Re[bm + tid], sre[tid]);
}

// ------------------------- launch -------------------------
extern "C" void kernel_launch(void* const* d_in, const int* in_sizes, int n_in,
                              void* d_out, int out_size) {
    (void)in_sizes; (void)n_in; (void)out_size;
    const float* alpha = (const float*)d_in[0];
    const float* dbow  = (const float*)d_in[1];
    const float* temb  = (const float*)d_in[2];
    const float* wemb  = (const float*)d_in[3];
    float* out   = (float*)d_out;
    float* Re    = out;            // [0 .. 2047]
    float* stdr  = out + BB;       // [2048]
    float* theta = out + BB + 1;   // [2049 ...]

    cudaMemsetAsync(out, 0, (BB + 1) * sizeof(float));

    theta_kernel<<<BB, 256>>>(alpha, theta);
    conv_ta<<<(256 * KEMB + 255) / 256, 256>>>(temb);
    conv_wb<<<(KEMB * (VVP / 2) + 255) / 256, 256>>>(wemb);

    wt_mma_kernel<<<dim3((VV + 127) / 128, 2), 256>>>();

    rowmax_seg<<<dim3(NSEG, TT), 256>>>();
    expsum_topk_seg<<<dim3(NSEG, TT), 256>>>();
    candmerge_kernel<<<TT, 32>>>();
    stdr_kernel<<<TT, 256>>>(stdr);

    normalize_bf16<<<(TTP * (VVP / 2) + 255) / 256, 256>>>();

    fused_re_mma<<<dim3((VV + 127) / 128, BB / 128), 256>>>(dbow, Re);
}

// round 3
// speedup vs baseline: 3.8356x; 1.0365x over previous
#include <cuda_runtime.h>
#include <cuda_bf16.h>
#include <cstdint>

#define VV 50000
#define VVP 50048            // padded vocab
#define TT 200
#define TTP 208              // padded topic dim (13*16)
#define KEMB 512
#define BB 2048
#define TK 20
#define NSEG 8
#define SEGLEN 6250

// ------------------------- static device scratch -------------------------
__device__ float g_wt[(size_t)TT * VV];                 // wt fp32 (40MB)
__device__ __nv_bfloat16 g_wtb[(size_t)TTP * VVP];      // e = exp(wt-max), bf16, padded rows/cols stay 0
__device__ __nv_bfloat16 g_ta[256 * KEMB];              // topic_emb bf16 padded rows
__device__ __nv_bfloat16 g_thb[(size_t)BB * TTP];       // theta' = theta * rowinv[t], bf16
__device__ unsigned g_rowmax_enc[TT];
__device__ float g_segsum[TT * NSEG];
__device__ float g_cand_v[TT * NSEG * TK];
__device__ int   g_cand_i[TT * NSEG * TK];
__device__ float g_topv[TT * TK];
__device__ int   g_topi[TT * TK];
__device__ float g_sq[TT];
__device__ float g_rowinv[TT];

// ------------------------- helpers -------------------------
__device__ __forceinline__ uint32_t smem_u32(const void* p) {
    return (uint32_t)__cvta_generic_to_shared(p);
}
__device__ __forceinline__ void ldsm_x4(uint32_t& r0, uint32_t& r1, uint32_t& r2, uint32_t& r3,
                                        uint32_t addr) {
    asm volatile("ldmatrix.sync.aligned.m8n8.x4.shared.b16 {%0,%1,%2,%3}, [%4];\n"
                 : "=r"(r0), "=r"(r1), "=r"(r2), "=r"(r3) : "r"(addr));
}
__device__ __forceinline__ void mma_bf16(float* d, const uint32_t* a, const uint32_t* b) {
    asm volatile(
        "mma.sync.aligned.m16n8k16.row.col.f32.bf16.bf16.f32 "
        "{%0,%1,%2,%3},{%4,%5,%6,%7},{%8,%9},{%0,%1,%2,%3};\n"
        : "+f"(d[0]), "+f"(d[1]), "+f"(d[2]), "+f"(d[3])
        : "r"(a[0]), "r"(a[1]), "r"(a[2]), "r"(a[3]), "r"(b[0]), "r"(b[1]));
}
__device__ __forceinline__ void cp_async16(uint32_t saddr, const void* gaddr) {
    asm volatile("cp.async.cg.shared.global [%0], [%1], 16;\n" :: "r"(saddr), "l"(gaddr));
}
__device__ __forceinline__ unsigned long long makekey(float v, int i) {
    return ((unsigned long long)__float_as_uint(v) << 32) |
           (unsigned long long)(0xFFFFFFFFu - (unsigned)i);
}
__device__ __forceinline__ unsigned fenc(float f) {
    unsigned b = __float_as_uint(f);
    return (b & 0x80000000u) ? ~b : (b | 0x80000000u);
}
__device__ __forceinline__ float fdec(unsigned e) {
    unsigned b = (e & 0x80000000u) ? (e & 0x7fffffffu) : ~e;
    return __uint_as_float(b);
}

// ------------------------- init: zero Re/stdr + rowmax sentinels -------------------------
__global__ void init_kernel(float* __restrict__ out) {
    int i = blockIdx.x * 256 + threadIdx.x;
    if (i < BB + 1) out[i] = 0.f;
    if (i < TT) g_rowmax_enc[i] = 0u;
}

// ------------------------- theta = softmax(alpha) -------------------------
__global__ void theta_kernel(const float* __restrict__ alpha, float* __restrict__ theta) {
    int row = blockIdx.x;
    int tid = threadIdx.x;
    __shared__ float red[256];
    float x = (tid < TT) ? alpha[row * TT + tid] : -1e30f;
    red[tid] = x;
    __syncthreads();
    for (int s = 128; s > 0; s >>= 1) {
        if (tid < s) red[tid] = fmaxf(red[tid], red[tid + s]);
        __syncthreads();
    }
    float m = red[0];
    __syncthreads();
    float e = (tid < TT) ? __expf(x - m) : 0.f;
    red[tid] = e;
    __syncthreads();
    for (int s = 128; s > 0; s >>= 1) {
        if (tid < s) red[tid] += red[tid + s];
        __syncthreads();
    }
    float inv = 1.f / red[0];
    if (tid < TT) theta[row * TT + tid] = e * inv;
}

// ------------------------- topic_emb -> bf16 (padded to 256 rows) -------------------------
__global__ void conv_ta(const float* __restrict__ temb) {
    int i = blockIdx.x * 256 + threadIdx.x;
    if (i < 256 * KEMB) {
        int r = i >> 9, c = i & 511;
        float v = (r < TT) ? temb[r * KEMB + c] : 0.f;
        g_ta[i] = __float2bfloat16(v);
    }
}

// ------------------------- wt = topic_emb @ word_emb (fp32 B inline-converted) + rowmax ----
__global__ __launch_bounds__(256) void wt_mma_kernel(const float* __restrict__ wemb) {
    __shared__ __align__(16) __nv_bfloat16 As[2][128 * 24];
    __shared__ __align__(16) __nv_bfloat16 Bs[2][16 * 136];
    const int tid = threadIdx.x, lane = tid & 31, wid = tid >> 5;
    const int warp_m = wid >> 2, warp_n = wid & 3;
    const int bm = blockIdx.y * 128, vb = blockIdx.x * 128;
    const int a_row = tid >> 1, a_half = tid & 1;
    const int b_row = tid >> 4, b_seg = tid & 15;
    const int bcol = vb + b_seg * 8;

    uint4 ra = *reinterpret_cast<const uint4*>(g_ta + (size_t)(bm + a_row) * KEMB + a_half * 8);
    float4 fb0 = make_float4(0, 0, 0, 0), fb1 = make_float4(0, 0, 0, 0);
    if (bcol < VV) {
        fb0 = *reinterpret_cast<const float4*>(wemb + (size_t)b_row * VV + bcol);
        fb1 = *reinterpret_cast<const float4*>(wemb + (size_t)b_row * VV + bcol + 4);
    }
    *reinterpret_cast<uint4*>(&As[0][a_row * 24 + a_half * 8]) = ra;
    {
        __nv_bfloat162 p0 = __floats2bfloat162_rn(fb0.x, fb0.y);
        __nv_bfloat162 p1 = __floats2bfloat162_rn(fb0.z, fb0.w);
        __nv_bfloat162 p2 = __floats2bfloat162_rn(fb1.x, fb1.y);
        __nv_bfloat162 p3 = __floats2bfloat162_rn(fb1.z, fb1.w);
        uint4 bb = make_uint4(*(uint32_t*)&p0, *(uint32_t*)&p1, *(uint32_t*)&p2, *(uint32_t*)&p3);
        *reinterpret_cast<uint4*>(&Bs[0][b_row * 136 + b_seg * 8]) = bb;
    }
    __syncthreads();

    float acc[4][4][4] = {};
    const int a_off = ((warp_m * 64 + (lane & 15)) * 24 + (lane >> 4) * 8) * 2;
    const int b_off = (((lane & 7) + ((lane >> 3) & 1) * 8) * 136 + warp_n * 32 + (lane >> 4) * 8) * 2;

    const int NK = KEMB / 16;
    for (int c = 0; c < NK; ++c) {
        if (c < NK - 1) {
            int k0 = (c + 1) * 16;
            ra = *reinterpret_cast<const uint4*>(g_ta + (size_t)(bm + a_row) * KEMB + k0 + a_half * 8);
            if (bcol < VV) {
                fb0 = *reinterpret_cast<const float4*>(wemb + (size_t)(k0 + b_row) * VV + bcol);
                fb1 = *reinterpret_cast<const float4*>(wemb + (size_t)(k0 + b_row) * VV + bcol + 4);
            }
        }
        int cur = c & 1;
        uint32_t ab = smem_u32(&As[cur][0]) + a_off;
        uint32_t bb = smem_u32(&Bs[cur][0]) + b_off;
        uint32_t a[4][4], b[4][2];
        #pragma unroll
        for (int mi = 0; mi < 4; mi++)
            ldsm_x4(a[mi][0], a[mi][1], a[mi][2], a[mi][3], ab + mi * 16 * 24 * 2);
        ldsm_x4(b[0][0], b[0][1], b[1][0], b[1][1], bb);
        ldsm_x4(b[2][0], b[2][1], b[3][0], b[3][1], bb + 32);
        #pragma unroll
        for (int mi = 0; mi < 4; mi++)
            #pragma unroll
            for (int ni = 0; ni < 4; ni++)
                mma_bf16(acc[mi][ni], a[mi], b[ni]);
        if (c < NK - 1) {
            int nxt = 1 - cur;
            *reinterpret_cast<uint4*>(&As[nxt][a_row * 24 + a_half * 8]) = ra;
            __nv_bfloat162 p0 = __floats2bfloat162_rn(fb0.x, fb0.y);
            __nv_bfloat162 p1 = __floats2bfloat162_rn(fb0.z, fb0.w);
            __nv_bfloat162 p2 = __floats2bfloat162_rn(fb1.x, fb1.y);
            __nv_bfloat162 p3 = __floats2bfloat162_rn(fb1.z, fb1.w);
            uint4 bpk = make_uint4(*(uint32_t*)&p0, *(uint32_t*)&p1, *(uint32_t*)&p2, *(uint32_t*)&p3);
            *reinterpret_cast<uint4*>(&Bs[nxt][b_row * 136 + b_seg * 8]) = bpk;
            __syncthreads();
        }
    }

    // store wt + per-row max (encoded atomicMax)
    #pragma unroll
    for (int mi = 0; mi < 4; mi++) {
        int r0 = bm + warp_m * 64 + mi * 16 + (lane >> 2);
        float mx0 = -1e30f, mx1 = -1e30f;
        #pragma unroll
        for (int ni = 0; ni < 4; ni++) {
            int n0 = vb + warp_n * 32 + ni * 8 + (lane & 3) * 2;
            if (n0 < VV) {
                if (r0 < TT) {
                    float2 s = make_float2(acc[mi][ni][0], acc[mi][ni][1]);
                    *reinterpret_cast<float2*>(g_wt + (size_t)r0 * VV + n0) = s;
                    mx0 = fmaxf(mx0, fmaxf(s.x, s.y));
                }
                if (r0 + 8 < TT) {
                    float2 s = make_float2(acc[mi][ni][2], acc[mi][ni][3]);
                    *reinterpret_cast<float2*>(g_wt + (size_t)(r0 + 8) * VV + n0) = s;
                    mx1 = fmaxf(mx1, fmaxf(s.x, s.y));
                }
            }
        }
        mx0 = fmaxf(mx0, __shfl_xor_sync(0xffffffff, mx0, 1));
        mx0 = fmaxf(mx0, __shfl_xor_sync(0xffffffff, mx0, 2));
        mx1 = fmaxf(mx1, __shfl_xor_sync(0xffffffff, mx1, 1));
        mx1 = fmaxf(mx1, __shfl_xor_sync(0xffffffff, mx1, 2));
        if ((lane & 3) == 0) {
            if (r0 < TT) atomicMax(&g_rowmax_enc[r0], fenc(mx0));
            if (r0 + 8 < TT) atomicMax(&g_rowmax_enc[r0 + 8], fenc(mx1));
        }
    }
}

// ------------------------- exp + segsum + segment top-20, write e bf16 -------------------------
__global__ __launch_bounds__(256) void expsum_topk_seg() {
    int row = blockIdx.y, seg = blockIdx.x;
    int tid = threadIdx.x, lane = tid & 31, wid = tid >> 5;
    float m = fdec(g_rowmax_enc[row]);
    const float* p = g_wt + (size_t)row * VV + seg * SEGLEN;
    __nv_bfloat16* pe = g_wtb + (size_t)row * VVP + seg * SEGLEN;
    const int base = seg * SEGLEN;

    float lv[TK]; int li[TK];
    #pragma unroll
    for (int t = 0; t < TK; t++) { lv[t] = -1.f; li[t] = 0x7fffffff; }
    float ssum = 0.f;
    for (int i = tid; i < SEGLEN; i += 256) {
        float e = __expf(p[i] - m);
        pe[i] = __float2bfloat16(e);
        ssum += e;
        if (e > lv[TK - 1]) {
            int pos = TK - 1;
            while (pos > 0 && e > lv[pos - 1]) {
                lv[pos] = lv[pos - 1]; li[pos] = li[pos - 1]; pos--;
            }
            lv[pos] = e; li[pos] = base + i;
        }
    }
    #pragma unroll
    for (int off = 16; off > 0; off >>= 1) ssum += __shfl_xor_sync(0xffffffff, ssum, off);
    __shared__ float wsum[8];
    if (lane == 0) wsum[wid] = ssum;

    __shared__ float wv8[8][TK];
    __shared__ int   wi8[8][TK];
    int ptr = 0;
    for (int r = 0; r < TK; r++) {
        unsigned long long key = (ptr < TK) ? makekey(lv[ptr], li[ptr]) : 0ULL;
        unsigned long long k = key;
        #pragma unroll
        for (int off = 16; off > 0; off >>= 1) {
            unsigned long long o = __shfl_xor_sync(0xffffffff, k, off);
            if (o > k) k = o;
        }
        if (key == k && key != 0ULL) ptr++;
        if (lane == 0) {
            wv8[wid][r] = __uint_as_float((unsigned)(k >> 32));
            wi8[wid][r] = (int)(0xFFFFFFFFu - (unsigned)(k & 0xFFFFFFFFu));
        }
    }
    __syncthreads();
    if (tid == 0) {
        float t = 0.f;
        #pragma unroll
        for (int i = 0; i < 8; i++) t += wsum[i];
        g_segsum[row * NSEG + seg] = t;
    }
    if (wid == 0) {
        unsigned long long ck[5];
        #pragma unroll
        for (int j = 0; j < 5; j++) {
            int q = lane * 5 + j;
            ck[j] = makekey(wv8[q / TK][q % TK], wi8[q / TK][q % TK]);
        }
        for (int r = 0; r < TK; r++) {
            unsigned long long best = 0ULL; int bj = -1;
            #pragma unroll
            for (int j = 0; j < 5; j++)
                if (ck[j] > best) { best = ck[j]; bj = j; }
            unsigned long long k = best;
            #pragma unroll
            for (int off = 16; off > 0; off >>= 1) {
                unsigned long long o = __shfl_xor_sync(0xffffffff, k, off);
                if (o > k) k = o;
            }
            if (bj >= 0 && ck[bj] == k) ck[bj] = 0ULL;
            if (lane == 0) {
                g_cand_v[(row * NSEG + seg) * TK + r] = __uint_as_float((unsigned)(k >> 32));
                g_cand_i[(row * NSEG + seg) * TK + r] = (int)(0xFFFFFFFFu - (unsigned)(k & 0xFFFFFFFFu));
            }
        }
    }
}

// ------------------------- merge candidates -> top-20, normalize, rowinv -------------------------
__global__ void candmerge_kernel() {
    int row = blockIdx.x;
    int lane = threadIdx.x;
    unsigned long long ck[5];
    #pragma unroll
    for (int j = 0; j < 5; j++) {
        int q = lane * 5 + j;
        ck[j] = makekey(g_cand_v[row * (NSEG * TK) + q], g_cand_i[row * (NSEG * TK) + q]);
    }
    float selv[TK]; int seli[TK];
    for (int r = 0; r < TK; r++) {
        unsigned long long best = 0ULL; int bj = -1;
        #pragma unroll
        for (int j = 0; j < 5; j++)
            if (ck[j] > best) { best = ck[j]; bj = j; }
        unsigned long long k = best;
        #pragma unroll
        for (int off = 16; off > 0; off >>= 1) {
            unsigned long long o = __shfl_xor_sync(0xffffffff, k, off);
            if (o > k) k = o;
        }
        if (bj >= 0 && ck[bj] == k) ck[bj] = 0ULL;
        selv[r] = __uint_as_float((unsigned)(k >> 32));
        seli[r] = (int)(0xFFFFFFFFu - (unsigned)(k & 0xFFFFFFFFu));
    }
    if (lane == 0) {
        float s = 0.f;
        #pragma unroll
        for (int r = 0; r < TK; r++) s += selv[r];
        float inv = 1.f / s, sq = 0.f;
        #pragma unroll
        for (int r = 0; r < TK; r++) {
            float nv = selv[r] * inv;
            g_topv[row * TK + r] = nv;
            g_topi[row * TK + r] = seli[r];
            sq += nv * nv;
        }
        g_sq[row] = sq;
        float bs = 0.f;
        #pragma unroll
        for (int s8 = 0; s8 < NSEG; s8++) bs += g_segsum[row * NSEG + s8];
        g_rowinv[row] = 1.f / bs;
    }
}

// ------------------------- theta' = theta * rowinv[t] -> bf16 padded -------------------------
__global__ void scale_theta(const float* __restrict__ theta) {
    int row = blockIdx.x;
    int t = threadIdx.x;
    if (t < TT)
        g_thb[(size_t)row * TTP + t] = __float2bfloat16(theta[row * TT + t] * g_rowinv[t]);
    else if (t < TTP)
        g_thb[(size_t)row * TTP + t] = __float2bfloat16(0.f);
}

// ------------------------- STDR via sparse gram -------------------------
__global__ void stdr_kernel(float* __restrict__ out_stdr) {
    int i = blockIdx.x;
    int tid = threadIdx.x;
    __shared__ float vi[TK]; __shared__ int ii[TK];
    __shared__ float red[256];
    if (tid < TK) { vi[tid] = g_topv[i * TK + tid]; ii[tid] = g_topi[i * TK + tid]; }
    __syncthreads();
    float part = 0.f;
    float sqi = g_sq[i];
    for (int j = tid; j < TT; j += 256) {
        float g = 0.f;
        for (int b = 0; b < TK; b++) {
            int jb = g_topi[j * TK + b];
            float vb = g_topv[j * TK + b];
            #pragma unroll
            for (int a = 0; a < TK; a++)
                if (ii[a] == jb) g += vi[a] * vb;
        }
        float d2 = sqi + g_sq[j] - 2.f * g;
        part += 0.5f * fmaxf(d2, 0.f);
    }
    red[tid] = part;
    __syncthreads();
    for (int s = 128; s > 0; s >>= 1) {
        if (tid < s) red[tid] += red[tid + s];
        __syncthreads();
    }
    if (tid == 0) atomicAdd(out_stdr, red[0] * (1.f / ((float)TT * (float)TT)));
}

// ------------------------- fused Re: full-K smem, cp.async dbow prefetch -------------------------
#define LDA 216   // 208 + 8 pad (bf16)
#define LDB 136   // 128 + 8 pad (bf16)
#define LDD 132   // 128 + 4 pad (fp32)

__global__ __launch_bounds__(256, 1) void fused_re_mma(const float* __restrict__ dbow,
                                                       float* __restrict__ Re) {
    extern __shared__ char smraw[];
    __nv_bfloat16* As = (__nv_bfloat16*)smraw;            // 128 x LDA
    __nv_bfloat16* Bs = As + 128 * LDA;                   // 208 x LDB
    float* Ds = (float*)(Bs + TTP * LDB);                 // 128 x LDD

    const int tid = threadIdx.x, lane = tid & 31, wid = tid >> 5;
    const int warp_m = wid >> 2, warp_n = wid & 3;
    const int bm = blockIdx.y * 128, vb = blockIdx.x * 128;

    // 1) prefetch dbow tile via cp.async (overlaps with everything below)
    #pragma unroll
    for (int i = 0; i < 16; i++) {
        int c = tid + i * 256;              // 4096 chunks of 16B
        int row = c >> 5;
        int col4 = (c & 31) * 4;
        int gcol = vb + col4;
        const float* gp = dbow + (size_t)(bm + row) * VV + gcol;
        float* sp = Ds + row * LDD + col4;
        if (gcol + 3 < VV) {
            cp_async16(smem_u32(sp), gp);
        } else {
            float4 z = make_float4(0.f, 0.f, 0.f, 0.f);
            if (gcol + 0 < VV) z.x = gp[0];
            if (gcol + 1 < VV) z.y = gp[1];
            if (gcol + 2 < VV) z.z = gp[2];
            if (gcol + 3 < VV) z.w = gp[3];
            *reinterpret_cast<float4*>(sp) = z;
        }
    }
    asm volatile("cp.async.commit_group;\n");

    // 2) load full A tile (128 x 208 bf16) and B tile (208 x 128 bf16)
    #pragma unroll
    for (int i = 0; i < 13; i++) {
        int idx = tid + i * 256;            // 3328 uint4
        int row = idx / 26, u = idx % 26;   // A: 26 uint4 per row
        uint4 v = *reinterpret_cast<const uint4*>(g_thb + (size_t)(bm + row) * TTP + u * 8);
        *reinterpret_cast<uint4*>(As + row * LDA + u * 8) = v;
    }
    #pragma unroll
    for (int i = 0; i < 13; i++) {
        int idx = tid + i * 256;            // 3328 uint4
        int k = idx >> 4, u = idx & 15;     // B: 16 uint4 per row
        uint4 v = *reinterpret_cast<const uint4*>(g_wtb + (size_t)k * VVP + vb + u * 8);
        *reinterpret_cast<uint4*>(Bs + k * LDB + u * 8) = v;
    }
    __syncthreads();

    // 3) mainloop: 13 K-chunks, pure smem
    float acc[4][4][4] = {};
    const uint32_t a_base = smem_u32(As) +
        ((warp_m * 64 + (lane & 15)) * LDA + (lane >> 4) * 8) * 2;
    const uint32_t b_base = smem_u32(Bs) +
        (((lane & 7) + ((lane >> 3) & 1) * 8) * LDB + warp_n * 32 + (lane >> 4) * 8) * 2;

    #pragma unroll
    for (int kc = 0; kc < 13; kc++) {
        uint32_t a[4][4], b[4][2];
        #pragma unroll
        for (int mi = 0; mi < 4; mi++)
            ldsm_x4(a[mi][0], a[mi][1], a[mi][2], a[mi][3],
                    a_base + mi * 16 * LDA * 2 + kc * 32);
        uint32_t bb = b_base + kc * 16 * LDB * 2;
        ldsm_x4(b[0][0], b[0][1], b[1][0], b[1][1], bb);
        ldsm_x4(b[2][0], b[2][1], b[3][0], b[3][1], bb + 32);
        #pragma unroll
        for (int mi = 0; mi < 4; mi++)
            #pragma unroll
            for (int ni = 0; ni < 4; ni++)
                mma_bf16(acc[mi][ni], a[mi], b[ni]);
    }

    // 4) wait for dbow, epilogue
    asm volatile("cp.async.wait_group 0;\n");
    __syncthreads();

    float* sre = (float*)As;   // reuse A region
    if (tid < 128) sre[tid] = 0.f;
    __syncthreads();

    #pragma unroll
    for (int mi = 0; mi < 4; mi++) {
        int rl0 = warp_m * 64 + mi * 16 + (lane >> 2);
        float p0 = 0.f, p1 = 0.f;
        #pragma unroll
        for (int ni = 0; ni < 4; ni++) {
            int nl = warp_n * 32 + ni * 8 + (lane & 3) * 2;
            if (vb + nl < VV) {
                float2 d0 = *reinterpret_cast<const float2*>(Ds + rl0 * LDD + nl);
                float2 d1 = *reinterpret_cast<const float2*>(Ds + (rl0 + 8) * LDD + nl);
                p0 -= __logf(acc[mi][ni][0]) * d0.x + __logf(acc[mi][ni][1]) * d0.y;
                p1 -= __logf(acc[mi][ni][2]) * d1.x + __logf(acc[mi][ni][3]) * d1.y;
            }
        }
        p0 += __shfl_xor_sync(0xffffffff, p0, 1);
        p0 += __shfl_xor_sync(0xffffffff, p0, 2);
        p1 += __shfl_xor_sync(0xffffffff, p1, 1);
        p1 += __shfl_xor_sync(0xffffffff, p1, 2);
        if ((lane & 3) == 0) {
            atomicAdd(&sre[rl0], p0);
            atomicAdd(&sre[rl0 + 8], p1);
        }
    }
    __syncthreads();
    if (tid < 128) atomicAdd(&Re[bm + tid], sre[tid]);
}

// ------------------------- launch -------------------------
extern "C" void kernel_launch(void* const* d_in, const int* in_sizes, int n_in,
                              void* d_out, int out_size) {
    (void)in_sizes; (void)n_in; (void)out_size;
    const float* alpha = (const float*)d_in[0];
    const float* dbow  = (const float*)d_in[1];
    const float* temb  = (const float*)d_in[2];
    const float* wemb  = (const float*)d_in[3];
    float* out   = (float*)d_out;
    float* Re    = out;            // [0 .. 2047]
    float* stdr  = out + BB;       // [2048]
    float* theta = out + BB + 1;   // [2049 ...]

    init_kernel<<<(BB + 1 + 255) / 256, 256>>>(out);
    theta_kernel<<<BB, 256>>>(alpha, theta);
    conv_ta<<<(256 * KEMB + 255) / 256, 256>>>(temb);

    wt_mma_kernel<<<dim3((VV + 127) / 128, 2), 256>>>(wemb);

    expsum_topk_seg<<<dim3(NSEG, TT), 256>>>();
    candmerge_kernel<<<TT, 32>>>();
    scale_theta<<<BB, 256>>>(theta);
    stdr_kernel<<<TT, 256>>>(stdr);

    {
        size_t sm = (size_t)128 * LDA * 2 + (size_t)TTP * LDB * 2 + (size_t)128 * LDD * 4;
        cudaFuncSetAttribute(fused_re_mma,
                             cudaFuncAttributeMaxDynamicSharedMemorySize, (int)sm);
        fused_re_mma<<<dim3((VV + 127) / 128, BB / 128), 256, sm>>>(dbow, Re);
    }
}

// round 5
// speedup vs baseline: 6.0646x; 1.5811x over previous
#include <cuda_runtime.h>
#include <cuda_bf16.h>
#include <cstdint>

#define VV 50000
#define VVP 50048            // padded vocab
#define TT 200
#define TTP 208              // padded topic dim (13*16)
#define KEMB 512
#define BB 2048
#define TK 20
#define NSEG 8
#define SEGLEN 6250

// ------------------------- static device scratch -------------------------
__device__ float g_wt[(size_t)TT * VV];                 // wt fp32 (40MB)
__device__ __nv_bfloat16 g_wtb[(size_t)TTP * VVP];      // e = exp(wt-max) bf16, pad rows/cols stay 0
__device__ __nv_bfloat16 g_ta[256 * KEMB];              // topic_emb bf16 padded rows
__device__ __nv_bfloat16 g_thb[(size_t)BB * TTP];       // theta' = theta * rowinv[t], bf16
__device__ unsigned g_rowmax_enc[TT];
__device__ float g_segsum[TT * NSEG];
__device__ float g_cand_v[TT * NSEG * TK];
__device__ int   g_cand_i[TT * NSEG * TK];
__device__ float g_topv[TT * TK];
__device__ int   g_topi[TT * TK];
__device__ float g_sq[TT];
__device__ float g_rowinv[TT];

// ------------------------- helpers -------------------------
__device__ __forceinline__ uint32_t smem_u32(const void* p) {
    return (uint32_t)__cvta_generic_to_shared(p);
}
__device__ __forceinline__ void ldsm_x4(uint32_t& r0, uint32_t& r1, uint32_t& r2, uint32_t& r3,
                                        uint32_t addr) {
    asm volatile("ldmatrix.sync.aligned.m8n8.x4.shared.b16 {%0,%1,%2,%3}, [%4];\n"
                 : "=r"(r0), "=r"(r1), "=r"(r2), "=r"(r3) : "r"(addr));
}
__device__ __forceinline__ void mma_bf16(float* d, const uint32_t* a, const uint32_t* b) {
    asm volatile(
        "mma.sync.aligned.m16n8k16.row.col.f32.bf16.bf16.f32 "
        "{%0,%1,%2,%3},{%4,%5,%6,%7},{%8,%9},{%0,%1,%2,%3};\n"
        : "+f"(d[0]), "+f"(d[1]), "+f"(d[2]), "+f"(d[3])
        : "r"(a[0]), "r"(a[1]), "r"(a[2]), "r"(a[3]), "r"(b[0]), "r"(b[1]));
}
__device__ __forceinline__ unsigned long long makekey(float v, int i) {
    // valid for v >= 0
    return ((unsigned long long)__float_as_uint(v) << 32) |
           (unsigned long long)(0xFFFFFFFFu - (unsigned)i);
}
__device__ __forceinline__ unsigned fenc(float f) {
    unsigned b = __float_as_uint(f);
    return (b & 0x80000000u) ? ~b : (b | 0x80000000u);
}
__device__ __forceinline__ float fdec(unsigned e) {
    unsigned b = (e & 0x80000000u) ? (e & 0x7fffffffu) : ~e;
    return __uint_as_float(b);
}

// ------------------------- init -------------------------
__global__ void init_kernel(float* __restrict__ out) {
    int i = blockIdx.x * 256 + threadIdx.x;
    if (i < BB + 1) out[i] = 0.f;
    if (i < TT) g_rowmax_enc[i] = 0u;
}

// ------------------------- theta = softmax(alpha) -------------------------
__global__ void theta_kernel(const float* __restrict__ alpha, float* __restrict__ theta) {
    int row = blockIdx.x;
    int tid = threadIdx.x;
    __shared__ float red[256];
    float x = (tid < TT) ? alpha[row * TT + tid] : -1e30f;
    red[tid] = x;
    __syncthreads();
    for (int s = 128; s > 0; s >>= 1) {
        if (tid < s) red[tid] = fmaxf(red[tid], red[tid + s]);
        __syncthreads();
    }
    float m = red[0];
    __syncthreads();
    float e = (tid < TT) ? __expf(x - m) : 0.f;
    red[tid] = e;
    __syncthreads();
    for (int s = 128; s > 0; s >>= 1) {
        if (tid < s) red[tid] += red[tid + s];
        __syncthreads();
    }
    float inv = 1.f / red[0];
    if (tid < TT) theta[row * TT + tid] = e * inv;
}

// ------------------------- topic_emb -> bf16 (padded to 256 rows) -------------------------
__global__ void conv_ta(const float* __restrict__ temb) {
    int i = blockIdx.x * 256 + threadIdx.x;
    if (i < 256 * KEMB) {
        int r = i >> 9, c = i & 511;
        float v = (r < TT) ? temb[r * KEMB + c] : 0.f;
        g_ta[i] = __float2bfloat16(v);
    }
}

// ------------------------- wt = topic_emb @ word_emb (mma.sync) + rowmax -------------------------
__global__ __launch_bounds__(256) void wt_mma_kernel(const float* __restrict__ wemb) {
    __shared__ __align__(16) __nv_bfloat16 As[2][128 * 24];
    __shared__ __align__(16) __nv_bfloat16 Bs[2][16 * 136];
    const int tid = threadIdx.x, lane = tid & 31, wid = tid >> 5;
    const int warp_m = wid >> 2, warp_n = wid & 3;
    const int bm = blockIdx.y * 128, vb = blockIdx.x * 128;
    const int a_row = tid >> 1, a_half = tid & 1;
    const int b_row = tid >> 4, b_seg = tid & 15;
    const int bcol = vb + b_seg * 8;

    uint4 ra = *reinterpret_cast<const uint4*>(g_ta + (size_t)(bm + a_row) * KEMB + a_half * 8);
    float4 fb0 = make_float4(0, 0, 0, 0), fb1 = make_float4(0, 0, 0, 0);
    if (bcol < VV) {
        fb0 = *reinterpret_cast<const float4*>(wemb + (size_t)b_row * VV + bcol);
        fb1 = *reinterpret_cast<const float4*>(wemb + (size_t)b_row * VV + bcol + 4);
    }
    *reinterpret_cast<uint4*>(&As[0][a_row * 24 + a_half * 8]) = ra;
    {
        __nv_bfloat162 p0 = __floats2bfloat162_rn(fb0.x, fb0.y);
        __nv_bfloat162 p1 = __floats2bfloat162_rn(fb0.z, fb0.w);
        __nv_bfloat162 p2 = __floats2bfloat162_rn(fb1.x, fb1.y);
        __nv_bfloat162 p3 = __floats2bfloat162_rn(fb1.z, fb1.w);
        uint4 bb = make_uint4(*(uint32_t*)&p0, *(uint32_t*)&p1, *(uint32_t*)&p2, *(uint32_t*)&p3);
        *reinterpret_cast<uint4*>(&Bs[0][b_row * 136 + b_seg * 8]) = bb;
    }
    __syncthreads();

    float acc[4][4][4] = {};
    const int a_off = ((warp_m * 64 + (lane & 15)) * 24 + (lane >> 4) * 8) * 2;
    const int b_off = (((lane & 7) + ((lane >> 3) & 1) * 8) * 136 + warp_n * 32 + (lane >> 4) * 8) * 2;

    const int NK = KEMB / 16;
    for (int c = 0; c < NK; ++c) {
        if (c < NK - 1) {
            int k0 = (c + 1) * 16;
            ra = *reinterpret_cast<const uint4*>(g_ta + (size_t)(bm + a_row) * KEMB + k0 + a_half * 8);
            if (bcol < VV) {
                fb0 = *reinterpret_cast<const float4*>(wemb + (size_t)(k0 + b_row) * VV + bcol);
                fb1 = *reinterpret_cast<const float4*>(wemb + (size_t)(k0 + b_row) * VV + bcol + 4);
            }
        }
        int cur = c & 1;
        uint32_t ab = smem_u32(&As[cur][0]) + a_off;
        uint32_t bb = smem_u32(&Bs[cur][0]) + b_off;
        uint32_t a[4][4], b[4][2];
        #pragma unroll
        for (int mi = 0; mi < 4; mi++)
            ldsm_x4(a[mi][0], a[mi][1], a[mi][2], a[mi][3], ab + mi * 16 * 24 * 2);
        ldsm_x4(b[0][0], b[0][1], b[1][0], b[1][1], bb);
        ldsm_x4(b[2][0], b[2][1], b[3][0], b[3][1], bb + 32);
        #pragma unroll
        for (int mi = 0; mi < 4; mi++)
            #pragma unroll
            for (int ni = 0; ni < 4; ni++)
                mma_bf16(acc[mi][ni], a[mi], b[ni]);
        if (c < NK - 1) {
            int nxt = 1 - cur;
            *reinterpret_cast<uint4*>(&As[nxt][a_row * 24 + a_half * 8]) = ra;
            __nv_bfloat162 p0 = __floats2bfloat162_rn(fb0.x, fb0.y);
            __nv_bfloat162 p1 = __floats2bfloat162_rn(fb0.z, fb0.w);
            __nv_bfloat162 p2 = __floats2bfloat162_rn(fb1.x, fb1.y);
            __nv_bfloat162 p3 = __floats2bfloat162_rn(fb1.z, fb1.w);
            uint4 bpk = make_uint4(*(uint32_t*)&p0, *(uint32_t*)&p1, *(uint32_t*)&p2, *(uint32_t*)&p3);
            *reinterpret_cast<uint4*>(&Bs[nxt][b_row * 136 + b_seg * 8]) = bpk;
            __syncthreads();
        }
    }

    #pragma unroll
    for (int mi = 0; mi < 4; mi++) {
        int r0 = bm + warp_m * 64 + mi * 16 + (lane >> 2);
        float mx0 = -1e30f, mx1 = -1e30f;
        #pragma unroll
        for (int ni = 0; ni < 4; ni++) {
            int n0 = vb + warp_n * 32 + ni * 8 + (lane & 3) * 2;
            if (n0 < VV) {
                if (r0 < TT) {
                    float2 s = make_float2(acc[mi][ni][0], acc[mi][ni][1]);
                    *reinterpret_cast<float2*>(g_wt + (size_t)r0 * VV + n0) = s;
                    mx0 = fmaxf(mx0, fmaxf(s.x, s.y));
                }
                if (r0 + 8 < TT) {
                    float2 s = make_float2(acc[mi][ni][2], acc[mi][ni][3]);
                    *reinterpret_cast<float2*>(g_wt + (size_t)(r0 + 8) * VV + n0) = s;
                    mx1 = fmaxf(mx1, fmaxf(s.x, s.y));
                }
            }
        }
        mx0 = fmaxf(mx0, __shfl_xor_sync(0xffffffff, mx0, 1));
        mx0 = fmaxf(mx0, __shfl_xor_sync(0xffffffff, mx0, 2));
        mx1 = fmaxf(mx1, __shfl_xor_sync(0xffffffff, mx1, 1));
        mx1 = fmaxf(mx1, __shfl_xor_sync(0xffffffff, mx1, 2));
        if ((lane & 3) == 0) {
            if (r0 < TT) atomicMax(&g_rowmax_enc[r0], fenc(mx0));
            if (r0 + 8 < TT) atomicMax(&g_rowmax_enc[r0 + 8], fenc(mx1));
        }
    }
}

// ------------------------- exp + segsum + segment top-20 (register-only insert) -----------
__global__ __launch_bounds__(256) void expsum_topk_seg() {
    int row = blockIdx.y, seg = blockIdx.x;
    int tid = threadIdx.x, lane = tid & 31, wid = tid >> 5;
    float m = fdec(g_rowmax_enc[row]);
    const float* p = g_wt + (size_t)row * VV + seg * SEGLEN;
    __nv_bfloat16* pe = g_wtb + (size_t)row * VVP + seg * SEGLEN;
    const int base = seg * SEGLEN;

    float lv[TK]; int li[TK];
    #pragma unroll
    for (int t = 0; t < TK; t++) { lv[t] = 0.f; li[t] = 0x7fffffff; }
    float ssum = 0.f;
    for (int i = tid; i < SEGLEN; i += 256) {
        float e = __expf(p[i] - m);
        pe[i] = __float2bfloat16(e);
        ssum += e;
        if (e > lv[TK - 1]) {
            bool gt[TK];
            #pragma unroll
            for (int t = 0; t < TK; t++) gt[t] = (e > lv[t]);
            #pragma unroll
            for (int t = TK - 1; t >= 1; t--)
                if (gt[t - 1]) { lv[t] = lv[t - 1]; li[t] = li[t - 1]; }
            #pragma unroll
            for (int t = 0; t < TK; t++) {
                bool pl = gt[t] && (t == 0 || !gt[t - 1]);
                if (pl) { lv[t] = e; li[t] = base + i; }
            }
        }
    }
    #pragma unroll
    for (int off = 16; off > 0; off >>= 1) ssum += __shfl_xor_sync(0xffffffff, ssum, off);
    __shared__ float wsum[8];
    if (lane == 0) wsum[wid] = ssum;

    // warp merge via head/shift (static indices only)
    __shared__ float wv8[8][TK];
    __shared__ int   wi8[8][TK];
    unsigned long long head = makekey(lv[0], li[0]);
    for (int r = 0; r < TK; r++) {
        unsigned long long k = head;
        #pragma unroll
        for (int off = 16; off > 0; off >>= 1) {
            unsigned long long o = __shfl_xor_sync(0xffffffff, k, off);
            if (o > k) k = o;
        }
        if (head == k) {
            #pragma unroll
            for (int t = 0; t < TK - 1; t++) { lv[t] = lv[t + 1]; li[t] = li[t + 1]; }
            lv[TK - 1] = 0.f; li[TK - 1] = 0x7fffffff;
            head = makekey(lv[0], li[0]);
        }
        if (lane == 0) {
            wv8[wid][r] = __uint_as_float((unsigned)(k >> 32));
            wi8[wid][r] = (int)(0xFFFFFFFFu - (unsigned)(k & 0xFFFFFFFFu));
        }
    }
    __syncthreads();
    if (tid == 0) {
        float t = 0.f;
        #pragma unroll
        for (int i = 0; i < 8; i++) t += wsum[i];
        g_segsum[row * NSEG + seg] = t;
    }
    if (wid == 0) {
        unsigned long long ck[5];
        #pragma unroll
        for (int j = 0; j < 5; j++) {
            int q = lane * 5 + j;
            ck[j] = makekey(wv8[q / TK][q % TK], wi8[q / TK][q % TK]);
        }
        for (int r = 0; r < TK; r++) {
            unsigned long long best = 0ULL;
            #pragma unroll
            for (int j = 0; j < 5; j++) if (ck[j] > best) best = ck[j];
            unsigned long long k = best;
            #pragma unroll
            for (int off = 16; off > 0; off >>= 1) {
                unsigned long long o = __shfl_xor_sync(0xffffffff, k, off);
                if (o > k) k = o;
            }
            #pragma unroll
            for (int j = 0; j < 5; j++) if (ck[j] == k) ck[j] = 0ULL;
            if (lane == 0) {
                g_cand_v[(row * NSEG + seg) * TK + r] = __uint_as_float((unsigned)(k >> 32));
                g_cand_i[(row * NSEG + seg) * TK + r] = (int)(0xFFFFFFFFu - (unsigned)(k & 0xFFFFFFFFu));
            }
        }
    }
}

// ------------------------- merge candidates -> top-20, normalize, rowinv -------------------------
__global__ void candmerge_kernel() {
    int row = blockIdx.x;
    int lane = threadIdx.x;
    unsigned long long ck[5];
    #pragma unroll
    for (int j = 0; j < 5; j++) {
        int q = lane * 5 + j;
        ck[j] = makekey(g_cand_v[row * (NSEG * TK) + q], g_cand_i[row * (NSEG * TK) + q]);
    }
    float selv[TK]; int seli[TK];
    for (int r = 0; r < TK; r++) {
        unsigned long long best = 0ULL;
        #pragma unroll
        for (int j = 0; j < 5; j++) if (ck[j] > best) best = ck[j];
        unsigned long long k = best;
        #pragma unroll
        for (int off = 16; off > 0; off >>= 1) {
            unsigned long long o = __shfl_xor_sync(0xffffffff, k, off);
            if (o > k) k = o;
        }
        #pragma unroll
        for (int j = 0; j < 5; j++) if (ck[j] == k) ck[j] = 0ULL;
        selv[r] = __uint_as_float((unsigned)(k >> 32));
        seli[r] = (int)(0xFFFFFFFFu - (unsigned)(k & 0xFFFFFFFFu));
    }
    if (lane == 0) {
        float s = 0.f;
        #pragma unroll
        for (int r = 0; r < TK; r++) s += selv[r];
        float inv = 1.f / s, sq = 0.f;
        #pragma unroll
        for (int r = 0; r < TK; r++) {
            float nv = selv[r] * inv;
            g_topv[row * TK + r] = nv;
            g_topi[row * TK + r] = seli[r];
            sq += nv * nv;
        }
        g_sq[row] = sq;
        float bs = 0.f;
        #pragma unroll
        for (int s8 = 0; s8 < NSEG; s8++) bs += g_segsum[row * NSEG + s8];
        g_rowinv[row] = 1.f / bs;
    }
}

// ------------------------- theta' = theta * rowinv[t] -> bf16 padded -------------------------
__global__ void scale_theta(const float* __restrict__ theta) {
    int row = blockIdx.x;
    int t = threadIdx.x;
    if (t < TT)
        g_thb[(size_t)row * TTP + t] = __float2bfloat16(theta[row * TT + t] * g_rowinv[t]);
    else if (t < TTP)
        g_thb[(size_t)row * TTP + t] = __float2bfloat16(0.f);
}

// ------------------------- STDR via sparse gram -------------------------
__global__ void stdr_kernel(float* __restrict__ out_stdr) {
    int i = blockIdx.x;
    int tid = threadIdx.x;
    __shared__ float vi[TK]; __shared__ int ii[TK];
    __shared__ float red[256];
    if (tid < TK) { vi[tid] = g_topv[i * TK + tid]; ii[tid] = g_topi[i * TK + tid]; }
    __syncthreads();
    float part = 0.f;
    float sqi = g_sq[i];
    for (int j = tid; j < TT; j += 256) {
        float g = 0.f;
        for (int b = 0; b < TK; b++) {
            int jb = g_topi[j * TK + b];
            float vb = g_topv[j * TK + b];
            #pragma unroll
            for (int a = 0; a < TK; a++)
                if (ii[a] == jb) g += vi[a] * vb;
        }
        float d2 = sqi + g_sq[j] - 2.f * g;
        part += 0.5f * fmaxf(d2, 0.f);
    }
    red[tid] = part;
    __syncthreads();
    for (int s = 128; s > 0; s >>= 1) {
        if (tid < s) red[tid] += red[tid + s];
        __syncthreads();
    }
    if (tid == 0) atomicAdd(out_stdr, red[0] * (1.f / ((float)TT * (float)TT)));
}

// ------------------------- fused Re: full-K smem, direct-global dbow epilogue -------------
#define LDA 216   // 208 + 8 pad (bf16)
#define LDB 136   // 128 + 8 pad (bf16)

__global__ __launch_bounds__(256, 2) void fused_re_mma(const float* __restrict__ dbow,
                                                       float* __restrict__ Re) {
    extern __shared__ char smraw[];
    __nv_bfloat16* As = (__nv_bfloat16*)smraw;            // 128 x LDA
    __nv_bfloat16* Bs = As + 128 * LDA;                   // 208 x LDB

    const int tid = threadIdx.x, lane = tid & 31, wid = tid >> 5;
    const int warp_m = wid >> 2, warp_n = wid & 3;
    const int bm = blockIdx.y * 128, vb = blockIdx.x * 128;

    // load full A tile (128 x 208 bf16) and B tile (208 x 128 bf16)
    #pragma unroll
    for (int i = 0; i < 13; i++) {
        int idx = tid + i * 256;            // 3328 uint4
        int row = idx / 26, u = idx % 26;
        uint4 v = *reinterpret_cast<const uint4*>(g_thb + (size_t)(bm + row) * TTP + u * 8);
        *reinterpret_cast<uint4*>(As + row * LDA + u * 8) = v;
    }
    #pragma unroll
    for (int i = 0; i < 13; i++) {
        int idx = tid + i * 256;
        int k = idx >> 4, u = idx & 15;
        uint4 v = *reinterpret_cast<const uint4*>(g_wtb + (size_t)k * VVP + vb + u * 8);
        *reinterpret_cast<uint4*>(Bs + k * LDB + u * 8) = v;
    }
    __syncthreads();

    // mainloop: 13 K-chunks, pure smem
    float acc[4][4][4] = {};
    const uint32_t a_base = smem_u32(As) +
        ((warp_m * 64 + (lane & 15)) * LDA + (lane >> 4) * 8) * 2;
    const uint32_t b_base = smem_u32(Bs) +
        (((lane & 7) + ((lane >> 3) & 1) * 8) * LDB + warp_n * 32 + (lane >> 4) * 8) * 2;

    #pragma unroll
    for (int kc = 0; kc < 13; kc++) {
        uint32_t a[4][4], b[4][2];
        #pragma unroll
        for (int mi = 0; mi < 4; mi++)
            ldsm_x4(a[mi][0], a[mi][1], a[mi][2], a[mi][3],
                    a_base + mi * 16 * LDA * 2 + kc * 32);
        uint32_t bb = b_base + kc * 16 * LDB * 2;
        ldsm_x4(b[0][0], b[0][1], b[1][0], b[1][1], bb);
        ldsm_x4(b[2][0], b[2][1], b[3][0], b[3][1], bb + 32);
        #pragma unroll
        for (int mi = 0; mi < 4; mi++)
            #pragma unroll
            for (int ni = 0; ni < 4; ni++)
                mma_bf16(acc[mi][ni], a[mi], b[ni]);
    }
    __syncthreads();

    // epilogue: dbow direct from global, -log(logit)*dbow, per-row reduce
    float* sre = (float*)As;   // reuse A region
    if (tid < 128) sre[tid] = 0.f;
    __syncthreads();

    #pragma unroll
    for (int mi = 0; mi < 4; mi++) {
        int r0 = bm + warp_m * 64 + mi * 16 + (lane >> 2);
        float p0 = 0.f, p1 = 0.f;
        #pragma unroll
        for (int ni = 0; ni < 4; ni++) {
            int n0 = vb + warp_n * 32 + ni * 8 + (lane & 3) * 2;
            if (n0 < VV) {
                float2 d0 = *reinterpret_cast<const float2*>(dbow + (size_t)r0 * VV + n0);
                float2 d1 = *reinterpret_cast<const float2*>(dbow + (size_t)(r0 + 8) * VV + n0);
                p0 -= __logf(acc[mi][ni][0]) * d0.x + __logf(acc[mi][ni][1]) * d0.y;
                p1 -= __logf(acc[mi][ni][2]) * d1.x + __logf(acc[mi][ni][3]) * d1.y;
            }
        }
        p0 += __shfl_xor_sync(0xffffffff, p0, 1);
        p0 += __shfl_xor_sync(0xffffffff, p0, 2);
        p1 += __shfl_xor_sync(0xffffffff, p1, 1);
        p1 += __shfl_xor_sync(0xffffffff, p1, 2);
        if ((lane & 3) == 0) {
            int rl = warp_m * 64 + mi * 16 + (lane >> 2);
            atomicAdd(&sre[rl], p0);
            atomicAdd(&sre[rl + 8], p1);
        }
    }
    __syncthreads();
    if (tid < 128) atomicAdd(&Re[bm + tid], sre[tid]);
}

// ------------------------- launch -------------------------
extern "C" void kernel_launch(void* const* d_in, const int* in_sizes, int n_in,
                              void* d_out, int out_size) {
    (void)in_sizes; (void)n_in; (void)out_size;
    const float* alpha = (const float*)d_in[0];
    const float* dbow  = (const float*)d_in[1];
    const float* temb  = (const float*)d_in[2];
    const float* wemb  = (const float*)d_in[3];
    float* out   = (float*)d_out;
    float* Re    = out;            // [0 .. 2047]
    float* stdr  = out + BB;       // [2048]
    float* theta = out + BB + 1;   // [2049 ...]

    init_kernel<<<(BB + 1 + 255) / 256, 256>>>(out);
    theta_kernel<<<BB, 256>>>(alpha, theta);
    conv_ta<<<(256 * KEMB + 255) / 256, 256>>>(temb);

    wt_mma_kernel<<<dim3((VV + 127) / 128, 2), 256>>>(wemb);

    expsum_topk_seg<<<dim3(NSEG, TT), 256>>>();
    candmerge_kernel<<<TT, 32>>>();
    scale_theta<<<BB, 256>>>(theta);
    stdr_kernel<<<TT, 256>>>(stdr);

    {
        size_t sm = (size_t)128 * LDA * 2 + (size_t)TTP * LDB * 2;
        cudaFuncSetAttribute(fused_re_mma,
                             cudaFuncAttributeMaxDynamicSharedMemorySize, (int)sm);
        fused_re_mma<<<dim3((VV + 127) / 128, BB / 128), 256, sm>>>(dbow, Re);
    }
}